// round 4
// baseline (speedup 1.0000x reference)
#include <cuda_runtime.h>
#include <cuda_bf16.h>

// GaussianSplatting preprocess v4:
//   out = concat(positions[N,3], cov[N,3,3], alphas[N], sh[N,4]) flattened.
//   cov = R (S S^T) R^T; sh = [C0, c1*C1, c0*C1, c2*C1].
// v4: TILE=512 (reg-capped for full occupancy), LDG/STS staging (v3's cp.async
// reverted: it cut occupancy without moving DRAM%), block-local passthrough
// copies for DRAM row locality, streaming hints everywhere.

#define SH_C0 0.282095f
#define SH_C1 0.488603f

constexpr int TILE = 512;

__global__ void __launch_bounds__(TILE, 4) gs_preprocess_kernel(
    const float* __restrict__ positions,  // [N,3]
    const float* __restrict__ colors,     // [N,3]
    const float* __restrict__ alphas,     // [N]
    const float* __restrict__ R,          // [N,3,3]
    const float* __restrict__ S,          // [N,3,3]
    float* __restrict__ out,              // [17N]
    int n)
{
    __shared__ float sh_col[TILE * 3];
    __shared__ float sh_R[TILE * 9];
    __shared__ float sh_S[TILE * 9];   // reused as cov staging buffer

    const int tid = threadIdx.x;
    const int block0 = blockIdx.x * TILE;

    float* __restrict__ out_cov   = out + 3LL * n;
    float* __restrict__ out_alpha = out + 12LL * n;
    float* __restrict__ out_sh    = out + 13LL * n;

    const int cnt = min(TILE, n - block0);
    const bool full = (cnt == TILE);

    // ---------------- passthrough copies for this tile (block-local) ----------------
    // positions: [block0*3, block0*3 + cnt*3); base block0*3 is float4-aligned
    {
        const long long base = (long long)block0 * 3;
        const int total = cnt * 3;
        const int v = total >> 2;
        const float4* p4 = (const float4*)(positions + base);
        float4* o4 = (float4*)(out + base);
        for (int idx = tid; idx < v; idx += TILE)
            __stcs(o4 + idx, __ldcs(p4 + idx));
        for (int idx = v * 4 + tid; idx < total; idx += TILE)
            out[base + idx] = positions[base + idx];
    }
    // alphas: [block0, block0+cnt); both bases float4-aligned (12n*4B = 48nB)
    {
        const int v = cnt >> 2;
        const float4* a4 = (const float4*)(alphas + block0);
        float4* o4 = (float4*)(out_alpha + block0);
        for (int idx = tid; idx < v; idx += TILE)
            __stcs(o4 + idx, __ldcs(a4 + idx));
        for (int idx = v * 4 + tid; idx < cnt; idx += TILE)
            out_alpha[block0 + idx] = alphas[block0 + idx];
    }

    // ---------------- stage colors, R, S into smem ----------------
    if (full) {
        const float4* __restrict__ c4 = (const float4*)(colors + (long long)block0 * 3);
        const float4* __restrict__ r4 = (const float4*)(R      + (long long)block0 * 9);
        const float4* __restrict__ s4 = (const float4*)(S      + (long long)block0 * 9);
        float4* shc4 = (float4*)sh_col;
        float4* shr4 = (float4*)sh_R;
        float4* shs4 = (float4*)sh_S;
        if (tid < TILE * 3 / 4) shc4[tid] = __ldcs(c4 + tid);
        #pragma unroll
        for (int idx = tid; idx < TILE * 9 / 4; idx += TILE) {
            shr4[idx] = __ldcs(r4 + idx);
            shs4[idx] = __ldcs(s4 + idx);
        }
    } else {
        for (int idx = tid; idx < cnt * 3; idx += TILE)
            sh_col[idx] = colors[(long long)block0 * 3 + idx];
        for (int idx = tid; idx < cnt * 9; idx += TILE)
            sh_R[idx] = R[(long long)block0 * 9 + idx];
        for (int idx = tid; idx < cnt * 9; idx += TILE)
            sh_S[idx] = S[(long long)block0 * 9 + idx];
    }
    __syncthreads();

    // ---------------- per-point math ----------------
    if (tid < cnt) {
        const long long i = block0 + tid;

        // ---- SH coeffs ----
        const float c0 = sh_col[tid * 3 + 0];
        const float c1 = sh_col[tid * 3 + 1];
        const float c2 = sh_col[tid * 3 + 2];
        if ((n & 3) == 0) {
            __stcs((float4*)out_sh + i,
                   make_float4(SH_C0, c1 * SH_C1, c0 * SH_C1, c2 * SH_C1));
        } else {
            out_sh[4 * i + 0] = SH_C0;
            out_sh[4 * i + 1] = c1 * SH_C1;
            out_sh[4 * i + 2] = c0 * SH_C1;
            out_sh[4 * i + 3] = c2 * SH_C1;
        }

        // ---- load r, s from smem (stride 9 -> conflict-free) ----
        float r[9], s[9];
        #pragma unroll
        for (int k = 0; k < 9; ++k) r[k] = sh_R[tid * 9 + k];
        #pragma unroll
        for (int k = 0; k < 9; ++k) s[k] = sh_S[tid * 9 + k];

        // ---- M = S S^T (symmetric) ----
        const float m00 = s[0]*s[0] + s[1]*s[1] + s[2]*s[2];
        const float m01 = s[0]*s[3] + s[1]*s[4] + s[2]*s[5];
        const float m02 = s[0]*s[6] + s[1]*s[7] + s[2]*s[8];
        const float m11 = s[3]*s[3] + s[4]*s[4] + s[5]*s[5];
        const float m12 = s[3]*s[6] + s[4]*s[7] + s[5]*s[8];
        const float m22 = s[6]*s[6] + s[7]*s[7] + s[8]*s[8];

        // ---- T = R*M, cov = T*R^T; write into sh_S (own region only) ----
        float t[9];
        #pragma unroll
        for (int a = 0; a < 3; ++a) {
            const float ra0 = r[3*a + 0];
            const float ra1 = r[3*a + 1];
            const float ra2 = r[3*a + 2];
            t[3*a + 0] = ra0*m00 + ra1*m01 + ra2*m02;
            t[3*a + 1] = ra0*m01 + ra1*m11 + ra2*m12;
            t[3*a + 2] = ra0*m02 + ra1*m12 + ra2*m22;
        }
        #pragma unroll
        for (int a = 0; a < 3; ++a)
            #pragma unroll
            for (int l = 0; l < 3; ++l)
                sh_S[tid * 9 + 3*a + l] =
                    t[3*a + 0]*r[3*l + 0] + t[3*a + 1]*r[3*l + 1] + t[3*a + 2]*r[3*l + 2];
    }
    __syncthreads();

    // ---- coalesced cov store (base 3n + blk*9 floats; aligned iff n%4==0) ----
    if (full && (n & 3) == 0) {
        float4* o4 = (float4*)(out_cov + (long long)block0 * 9);
        const float4* shs4 = (const float4*)sh_S;
        #pragma unroll
        for (int idx = tid; idx < TILE * 9 / 4; idx += TILE)
            __stcs(o4 + idx, shs4[idx]);
    } else {
        for (int idx = tid; idx < cnt * 9; idx += TILE)
            out_cov[(long long)block0 * 9 + idx] = sh_S[idx];
    }
}

extern "C" void kernel_launch(void* const* d_in, const int* in_sizes, int n_in,
                              void* d_out, int out_size)
{
    const float* positions = (const float*)d_in[0];
    const float* colors    = (const float*)d_in[1];
    const float* alphas    = (const float*)d_in[2];
    const float* R         = (const float*)d_in[3];
    const float* S         = (const float*)d_in[4];
    float* out = (float*)d_out;

    const int n = in_sizes[2];  // alphas count == N

    const int blocks = (n + TILE - 1) / TILE;
    gs_preprocess_kernel<<<blocks, TILE>>>(positions, colors, alphas, R, S, out, n);
}

// round 5
// speedup vs baseline: 1.0272x; 1.0272x over previous
#include <cuda_runtime.h>
#include <cuda_bf16.h>

// GaussianSplatting preprocess v5:
//   out = concat(positions[N,3], cov[N,3,3], alphas[N], sh[N,4]) flattened.
//   cov = R (S S^T) R^T; sh = [C0, c1*C1, c0*C1, c2*C1].
// v5 = R2 structure (TILE=256, LDG->STS staging; best: 48.9us kernel) with ONE
// change: passthrough copies issued block-locally BEFORE the staging barrier so
// their traffic overlaps staging-load latency. TILE=512 (R4) reverted.

#define SH_C0 0.282095f
#define SH_C1 0.488603f

constexpr int TILE = 256;

__global__ void __launch_bounds__(TILE) gs_preprocess_kernel(
    const float* __restrict__ positions,  // [N,3]
    const float* __restrict__ colors,     // [N,3]
    const float* __restrict__ alphas,     // [N]
    const float* __restrict__ R,          // [N,3,3]
    const float* __restrict__ S,          // [N,3,3]
    float* __restrict__ out,              // [17N]
    int n)
{
    __shared__ float sh_col[TILE * 3];
    __shared__ float sh_R[TILE * 9];
    __shared__ float sh_S[TILE * 9];   // reused as cov staging buffer

    const int tid = threadIdx.x;
    const int block0 = blockIdx.x * TILE;

    float* __restrict__ out_cov   = out + 3LL * n;
    float* __restrict__ out_alpha = out + 12LL * n;
    float* __restrict__ out_sh    = out + 13LL * n;

    const int cnt = min(TILE, n - block0);
    const bool full = (cnt == TILE);

    // ---------------- stage colors, R, S into smem (issue loads early) ----------------
    if (full) {
        const float4* __restrict__ c4 = (const float4*)(colors + (long long)block0 * 3);
        const float4* __restrict__ r4 = (const float4*)(R      + (long long)block0 * 9);
        const float4* __restrict__ s4 = (const float4*)(S      + (long long)block0 * 9);
        float4* shc4 = (float4*)sh_col;
        float4* shr4 = (float4*)sh_R;
        float4* shs4 = (float4*)sh_S;
        if (tid < TILE * 3 / 4) shc4[tid] = __ldcs(c4 + tid);
        #pragma unroll
        for (int idx = tid; idx < TILE * 9 / 4; idx += TILE) {
            shr4[idx] = __ldcs(r4 + idx);
            shs4[idx] = __ldcs(s4 + idx);
        }
    } else {
        for (int idx = tid; idx < cnt * 3; idx += TILE)
            sh_col[idx] = colors[(long long)block0 * 3 + idx];
        for (int idx = tid; idx < cnt * 9; idx += TILE)
            sh_R[idx] = R[(long long)block0 * 9 + idx];
        for (int idx = tid; idx < cnt * 9; idx += TILE)
            sh_S[idx] = S[(long long)block0 * 9 + idx];
    }

    // ---------------- passthrough copies (block-local, overlap staging latency) ----
    // positions: [block0*3, block0*3 + cnt*3); base block0*3 float4-aligned
    {
        const long long base = (long long)block0 * 3;
        const int total = cnt * 3;
        const int v = total >> 2;
        const float4* p4 = (const float4*)(positions + base);
        float4* o4 = (float4*)(out + base);
        for (int idx = tid; idx < v; idx += TILE)
            __stcs(o4 + idx, __ldcs(p4 + idx));
        for (int idx = v * 4 + tid; idx < total; idx += TILE)
            out[base + idx] = positions[base + idx];
    }
    // alphas: [block0, block0+cnt); dst base 12n floats = 48n B -> float4-aligned
    {
        const int v = cnt >> 2;
        const float4* a4 = (const float4*)(alphas + block0);
        float4* o4 = (float4*)(out_alpha + block0);
        for (int idx = tid; idx < v; idx += TILE)
            __stcs(o4 + idx, __ldcs(a4 + idx));
        for (int idx = v * 4 + tid; idx < cnt; idx += TILE)
            out_alpha[block0 + idx] = alphas[block0 + idx];
    }
    __syncthreads();

    // ---------------- per-point math ----------------
    if (tid < cnt) {
        const long long i = block0 + tid;

        // ---- SH coeffs ----
        const float c0 = sh_col[tid * 3 + 0];
        const float c1 = sh_col[tid * 3 + 1];
        const float c2 = sh_col[tid * 3 + 2];
        if ((n & 3) == 0) {
            __stcs((float4*)out_sh + i,
                   make_float4(SH_C0, c1 * SH_C1, c0 * SH_C1, c2 * SH_C1));
        } else {
            out_sh[4 * i + 0] = SH_C0;
            out_sh[4 * i + 1] = c1 * SH_C1;
            out_sh[4 * i + 2] = c0 * SH_C1;
            out_sh[4 * i + 3] = c2 * SH_C1;
        }

        // ---- load r, s from smem (stride 9 -> conflict-free) ----
        float r[9], s[9];
        #pragma unroll
        for (int k = 0; k < 9; ++k) r[k] = sh_R[tid * 9 + k];
        #pragma unroll
        for (int k = 0; k < 9; ++k) s[k] = sh_S[tid * 9 + k];

        // ---- M = S S^T (symmetric) ----
        const float m00 = s[0]*s[0] + s[1]*s[1] + s[2]*s[2];
        const float m01 = s[0]*s[3] + s[1]*s[4] + s[2]*s[5];
        const float m02 = s[0]*s[6] + s[1]*s[7] + s[2]*s[8];
        const float m11 = s[3]*s[3] + s[4]*s[4] + s[5]*s[5];
        const float m12 = s[3]*s[6] + s[4]*s[7] + s[5]*s[8];
        const float m22 = s[6]*s[6] + s[7]*s[7] + s[8]*s[8];

        // ---- T = R*M, cov = T*R^T; write into sh_S (own region only) ----
        float t[9];
        #pragma unroll
        for (int a = 0; a < 3; ++a) {
            const float ra0 = r[3*a + 0];
            const float ra1 = r[3*a + 1];
            const float ra2 = r[3*a + 2];
            t[3*a + 0] = ra0*m00 + ra1*m01 + ra2*m02;
            t[3*a + 1] = ra0*m01 + ra1*m11 + ra2*m12;
            t[3*a + 2] = ra0*m02 + ra1*m12 + ra2*m22;
        }
        #pragma unroll
        for (int a = 0; a < 3; ++a)
            #pragma unroll
            for (int l = 0; l < 3; ++l)
                sh_S[tid * 9 + 3*a + l] =
                    t[3*a + 0]*r[3*l + 0] + t[3*a + 1]*r[3*l + 1] + t[3*a + 2]*r[3*l + 2];
    }
    __syncthreads();

    // ---- coalesced cov store (base 3n + blk*9 floats; aligned iff n%4==0) ----
    if (full && (n & 3) == 0) {
        float4* o4 = (float4*)(out_cov + (long long)block0 * 9);
        const float4* shs4 = (const float4*)sh_S;
        #pragma unroll
        for (int idx = tid; idx < TILE * 9 / 4; idx += TILE)
            __stcs(o4 + idx, shs4[idx]);
    } else {
        for (int idx = tid; idx < cnt * 9; idx += TILE)
            out_cov[(long long)block0 * 9 + idx] = sh_S[idx];
    }
}

extern "C" void kernel_launch(void* const* d_in, const int* in_sizes, int n_in,
                              void* d_out, int out_size)
{
    const float* positions = (const float*)d_in[0];
    const float* colors    = (const float*)d_in[1];
    const float* alphas    = (const float*)d_in[2];
    const float* R         = (const float*)d_in[3];
    const float* S         = (const float*)d_in[4];
    float* out = (float*)d_out;

    const int n = in_sizes[2];  // alphas count == N

    const int blocks = (n + TILE - 1) / TILE;
    gs_preprocess_kernel<<<blocks, TILE>>>(positions, colors, alphas, R, S, out, n);
}

// round 6
// speedup vs baseline: 1.0759x; 1.0474x over previous
#include <cuda_runtime.h>
#include <cuda_bf16.h>

// GaussianSplatting preprocess v6:
//   out = concat(positions[N,3], cov[N,3,3], alphas[N], sh[N,4]) flattened.
//   cov = R (S S^T) R^T; sh = [C0, c1*C1, c0*C1, c2*C1].
// v6 = exact R2 structure (best: 48.9us kernel, occ 91%) with block-wide
// __syncthreads() replaced by warp-autonomous tiles + __syncwarp(): each warp
// stages/computes/stores its own 32 points, so warps never wait on each other.

#define SH_C0 0.282095f
#define SH_C1 0.488603f

constexpr int TILE = 256;   // points per block (8 warps x 32 points)

__global__ void __launch_bounds__(TILE) gs_preprocess_kernel(
    const float* __restrict__ positions,  // [N,3]
    const float* __restrict__ colors,     // [N,3]
    const float* __restrict__ alphas,     // [N]
    const float* __restrict__ R,          // [N,3,3]
    const float* __restrict__ S,          // [N,3,3]
    float* __restrict__ out,              // [17N]
    int n)
{
    __shared__ float sh_col[TILE * 3];
    __shared__ float sh_R[TILE * 9];
    __shared__ float sh_S[TILE * 9];   // reused as cov staging buffer

    const int tid  = threadIdx.x;
    const int lane = tid & 31;
    const int wid  = tid >> 5;
    const int block0 = blockIdx.x * TILE;
    const int wbase  = block0 + wid * 32;          // this warp's first point
    const int wcnt   = min(32, n - wbase);         // valid points in this warp

    float* __restrict__ out_cov   = out + 3LL * n;
    float* __restrict__ out_alpha = out + 12LL * n;
    float* __restrict__ out_sh    = out + 13LL * n;

    // warp-private smem slices
    float* sc = sh_col + wid * 96;    // 32*3
    float* sr = sh_R   + wid * 288;   // 32*9
    float* ss = sh_S   + wid * 288;   // 32*9 (later holds cov)

    if (wcnt == 32) {
        // ---- warp-local float4 staging (bases 16B-aligned: wbase%32==0) ----
        const float4* __restrict__ c4 = (const float4*)(colors + (long long)wbase * 3);
        const float4* __restrict__ r4 = (const float4*)(R      + (long long)wbase * 9);
        const float4* __restrict__ s4 = (const float4*)(S      + (long long)wbase * 9);
        float4* sc4 = (float4*)sc;
        float4* sr4 = (float4*)sr;
        float4* ss4 = (float4*)ss;
        if (lane < 24) sc4[lane] = c4[lane];       // 96 floats = 24 x float4
        #pragma unroll
        for (int idx = lane; idx < 72; idx += 32) { // 288 floats = 72 x float4
            sr4[idx] = r4[idx];
            ss4[idx] = s4[idx];
        }
        __syncwarp();

        // ---- per-point math (lane = point) ----
        const long long i = wbase + lane;

        const float c0 = sc[lane * 3 + 0];
        const float c1 = sc[lane * 3 + 1];
        const float c2 = sc[lane * 3 + 2];
        if ((n & 3) == 0) {
            ((float4*)out_sh)[i] =
                make_float4(SH_C0, c1 * SH_C1, c0 * SH_C1, c2 * SH_C1);
        } else {
            out_sh[4 * i + 0] = SH_C0;
            out_sh[4 * i + 1] = c1 * SH_C1;
            out_sh[4 * i + 2] = c0 * SH_C1;
            out_sh[4 * i + 3] = c2 * SH_C1;
        }

        float r[9], s[9];
        #pragma unroll
        for (int k = 0; k < 9; ++k) r[k] = sr[lane * 9 + k];
        #pragma unroll
        for (int k = 0; k < 9; ++k) s[k] = ss[lane * 9 + k];

        // M = S S^T (symmetric)
        const float m00 = s[0]*s[0] + s[1]*s[1] + s[2]*s[2];
        const float m01 = s[0]*s[3] + s[1]*s[4] + s[2]*s[5];
        const float m02 = s[0]*s[6] + s[1]*s[7] + s[2]*s[8];
        const float m11 = s[3]*s[3] + s[4]*s[4] + s[5]*s[5];
        const float m12 = s[3]*s[6] + s[4]*s[7] + s[5]*s[8];
        const float m22 = s[6]*s[6] + s[7]*s[7] + s[8]*s[8];

        // T = R*M, cov = T*R^T; write into warp's ss slice (own 9 floats)
        float t[9];
        #pragma unroll
        for (int a = 0; a < 3; ++a) {
            const float ra0 = r[3*a + 0];
            const float ra1 = r[3*a + 1];
            const float ra2 = r[3*a + 2];
            t[3*a + 0] = ra0*m00 + ra1*m01 + ra2*m02;
            t[3*a + 1] = ra0*m01 + ra1*m11 + ra2*m12;
            t[3*a + 2] = ra0*m02 + ra1*m12 + ra2*m22;
        }
        #pragma unroll
        for (int a = 0; a < 3; ++a)
            #pragma unroll
            for (int l = 0; l < 3; ++l)
                ss[lane * 9 + 3*a + l] =
                    t[3*a + 0]*r[3*l + 0] + t[3*a + 1]*r[3*l + 1] + t[3*a + 2]*r[3*l + 2];
        __syncwarp();

        // ---- warp-local coalesced cov store (base aligned iff n%4==0) ----
        if ((n & 3) == 0) {
            float4* o4 = (float4*)(out_cov + (long long)wbase * 9);
            #pragma unroll
            for (int idx = lane; idx < 72; idx += 32)
                o4[idx] = ss4[idx];
        } else {
            for (int idx = lane; idx < 288; idx += 32)
                out_cov[(long long)wbase * 9 + idx] = ss[idx];
        }
    } else if (wcnt > 0 && lane < wcnt) {
        // ---- partial warp: fully scalar direct path (rare tail) ----
        const long long i = wbase + lane;
        const long long p3 = 3 * i, p9 = 9 * i;

        const float c0 = colors[p3 + 0];
        const float c1 = colors[p3 + 1];
        const float c2 = colors[p3 + 2];
        out_sh[4 * i + 0] = SH_C0;
        out_sh[4 * i + 1] = c1 * SH_C1;
        out_sh[4 * i + 2] = c0 * SH_C1;
        out_sh[4 * i + 3] = c2 * SH_C1;

        float r[9], s[9];
        #pragma unroll
        for (int k = 0; k < 9; ++k) r[k] = R[p9 + k];
        #pragma unroll
        for (int k = 0; k < 9; ++k) s[k] = S[p9 + k];

        const float m00 = s[0]*s[0] + s[1]*s[1] + s[2]*s[2];
        const float m01 = s[0]*s[3] + s[1]*s[4] + s[2]*s[5];
        const float m02 = s[0]*s[6] + s[1]*s[7] + s[2]*s[8];
        const float m11 = s[3]*s[3] + s[4]*s[4] + s[5]*s[5];
        const float m12 = s[3]*s[6] + s[4]*s[7] + s[5]*s[8];
        const float m22 = s[6]*s[6] + s[7]*s[7] + s[8]*s[8];

        float t[9];
        #pragma unroll
        for (int a = 0; a < 3; ++a) {
            const float ra0 = r[3*a + 0];
            const float ra1 = r[3*a + 1];
            const float ra2 = r[3*a + 2];
            t[3*a + 0] = ra0*m00 + ra1*m01 + ra2*m02;
            t[3*a + 1] = ra0*m01 + ra1*m11 + ra2*m12;
            t[3*a + 2] = ra0*m02 + ra1*m12 + ra2*m22;
        }
        #pragma unroll
        for (int a = 0; a < 3; ++a)
            #pragma unroll
            for (int l = 0; l < 3; ++l)
                out_cov[p9 + 3*a + l] =
                    t[3*a + 0]*r[3*l + 0] + t[3*a + 1]*r[3*l + 1] + t[3*a + 2]*r[3*l + 2];
    }

    // ---------------- flat passthrough copies (exact R2 tail) ----------------
    const long long gtid    = (long long)blockIdx.x * TILE + tid;
    const long long gstride = (long long)gridDim.x * TILE;

    // positions: 3N floats
    {
        const long long nv = (3LL * n) >> 2;
        const float4* p4 = (const float4*)positions;
        float4* o4 = (float4*)out;
        for (long long idx = gtid; idx < nv; idx += gstride) o4[idx] = p4[idx];
        for (long long idx = nv * 4 + gtid; idx < 3LL * n; idx += gstride)
            out[idx] = positions[idx];
    }
    // alphas: N floats (dst base 48n B -> always 16B aligned)
    {
        const long long nv = (long long)n >> 2;
        const float4* a4 = (const float4*)alphas;
        float4* o4 = (float4*)out_alpha;
        for (long long idx = gtid; idx < nv; idx += gstride) o4[idx] = a4[idx];
        for (long long idx = nv * 4 + gtid; idx < n; idx += gstride)
            out_alpha[idx] = alphas[idx];
    }
}

extern "C" void kernel_launch(void* const* d_in, const int* in_sizes, int n_in,
                              void* d_out, int out_size)
{
    const float* positions = (const float*)d_in[0];
    const float* colors    = (const float*)d_in[1];
    const float* alphas    = (const float*)d_in[2];
    const float* R         = (const float*)d_in[3];
    const float* S         = (const float*)d_in[4];
    float* out = (float*)d_out;

    const int n = in_sizes[2];  // alphas count == N

    const int blocks = (n + TILE - 1) / TILE;
    gs_preprocess_kernel<<<blocks, TILE>>>(positions, colors, alphas, R, S, out, n);
}

// round 7
// speedup vs baseline: 1.0896x; 1.0127x over previous
#include <cuda_runtime.h>
#include <cuda_bf16.h>

// GaussianSplatting preprocess — FINAL (= R2 champion, reg-pinned):
//   out = concat(positions[N,3], cov[N,3,3], alphas[N], sh[N,4]) flattened.
//   cov = R (S S^T) R^T per point; sh = [C0, c1*C1, c0*C1, c2*C1].
// All global traffic float4-coalesced via smem staging of the AoS 3x3 data.
// Evidence across R3-R6: DRAM pins at ~74-75% (achievable HBM ceiling for this
// mixed r/w stream) regardless of structure; this config minimizes overhead
// (32 regs, occ 91%, kernel 48.9us). launch_bounds(...,8) pins 32 regs.

#define SH_C0 0.282095f
#define SH_C1 0.488603f

constexpr int TILE = 256;

__global__ void __launch_bounds__(TILE, 8) gs_preprocess_kernel(
    const float* __restrict__ positions,  // [N,3]
    const float* __restrict__ colors,     // [N,3]
    const float* __restrict__ alphas,     // [N]
    const float* __restrict__ R,          // [N,3,3]
    const float* __restrict__ S,          // [N,3,3]
    float* __restrict__ out,              // [17N]
    int n)
{
    __shared__ float sh_col[TILE * 3];
    __shared__ float sh_R[TILE * 9];
    __shared__ float sh_S[TILE * 9];   // reused as cov staging buffer

    const int tid = threadIdx.x;
    const int block0 = blockIdx.x * TILE;

    float* __restrict__ out_cov   = out + 3LL * n;
    float* __restrict__ out_alpha = out + 12LL * n;
    float* __restrict__ out_sh    = out + 13LL * n;

    // ---------------- tiled cov + sh work ----------------
    {
        const int cnt = min(TILE, n - block0);

        if (cnt == TILE) {
            // fully coalesced float4 staging (bases: blk*12B, blk*36B -> 16B aligned)
            const float4* __restrict__ c4 = (const float4*)(colors + (long long)block0 * 3);
            const float4* __restrict__ r4 = (const float4*)(R      + (long long)block0 * 9);
            const float4* __restrict__ s4 = (const float4*)(S      + (long long)block0 * 9);
            float4* shc4 = (float4*)sh_col;
            float4* shr4 = (float4*)sh_R;
            float4* shs4 = (float4*)sh_S;
            if (tid < TILE * 3 / 4) shc4[tid] = c4[tid];          // 192 loads
            #pragma unroll
            for (int idx = tid; idx < TILE * 9 / 4; idx += TILE)  // 576 loads
                shr4[idx] = r4[idx];
            #pragma unroll
            for (int idx = tid; idx < TILE * 9 / 4; idx += TILE)
                shs4[idx] = s4[idx];
        } else {
            for (int idx = tid; idx < cnt * 3; idx += TILE)
                sh_col[idx] = colors[(long long)block0 * 3 + idx];
            for (int idx = tid; idx < cnt * 9; idx += TILE)
                sh_R[idx] = R[(long long)block0 * 9 + idx];
            for (int idx = tid; idx < cnt * 9; idx += TILE)
                sh_S[idx] = S[(long long)block0 * 9 + idx];
        }
        __syncthreads();

        if (tid < cnt) {
            const long long i = block0 + tid;

            // ---- SH coeffs (direct float4 store when 13n is float4-aligned) ----
            const float c0 = sh_col[tid * 3 + 0];
            const float c1 = sh_col[tid * 3 + 1];
            const float c2 = sh_col[tid * 3 + 2];
            if ((n & 3) == 0) {
                ((float4*)out_sh)[i] =
                    make_float4(SH_C0, c1 * SH_C1, c0 * SH_C1, c2 * SH_C1);
            } else {
                out_sh[4 * i + 0] = SH_C0;
                out_sh[4 * i + 1] = c1 * SH_C1;
                out_sh[4 * i + 2] = c0 * SH_C1;
                out_sh[4 * i + 3] = c2 * SH_C1;
            }

            // ---- load r, s from smem (stride 9 -> bank-conflict-free) ----
            float r[9], s[9];
            #pragma unroll
            for (int k = 0; k < 9; ++k) r[k] = sh_R[tid * 9 + k];
            #pragma unroll
            for (int k = 0; k < 9; ++k) s[k] = sh_S[tid * 9 + k];

            // ---- M = S S^T (symmetric) ----
            const float m00 = s[0]*s[0] + s[1]*s[1] + s[2]*s[2];
            const float m01 = s[0]*s[3] + s[1]*s[4] + s[2]*s[5];
            const float m02 = s[0]*s[6] + s[1]*s[7] + s[2]*s[8];
            const float m11 = s[3]*s[3] + s[4]*s[4] + s[5]*s[5];
            const float m12 = s[3]*s[6] + s[4]*s[7] + s[5]*s[8];
            const float m22 = s[6]*s[6] + s[7]*s[7] + s[8]*s[8];

            // ---- T = R*M, cov = T*R^T; write into sh_S (own region only) ----
            float t[9];
            #pragma unroll
            for (int a = 0; a < 3; ++a) {
                const float ra0 = r[3*a + 0];
                const float ra1 = r[3*a + 1];
                const float ra2 = r[3*a + 2];
                t[3*a + 0] = ra0*m00 + ra1*m01 + ra2*m02;
                t[3*a + 1] = ra0*m01 + ra1*m11 + ra2*m12;
                t[3*a + 2] = ra0*m02 + ra1*m12 + ra2*m22;
            }
            #pragma unroll
            for (int a = 0; a < 3; ++a)
                #pragma unroll
                for (int l = 0; l < 3; ++l)
                    sh_S[tid * 9 + 3*a + l] =
                        t[3*a + 0]*r[3*l + 0] + t[3*a + 1]*r[3*l + 1] + t[3*a + 2]*r[3*l + 2];
        }
        __syncthreads();

        // ---- coalesced cov store (base: 3n + blk*9 floats; aligned iff n%4==0) ----
        if (cnt == TILE && (n & 3) == 0) {
            float4* o4 = (float4*)(out_cov + (long long)block0 * 9);
            const float4* shs4 = (const float4*)sh_S;
            #pragma unroll
            for (int idx = tid; idx < TILE * 9 / 4; idx += TILE)
                o4[idx] = shs4[idx];
        } else {
            for (int idx = tid; idx < cnt * 9; idx += TILE)
                out_cov[(long long)block0 * 9 + idx] = sh_S[idx];
        }
    }

    // ---------------- flat passthrough copies (positions, alphas) ----------------
    const long long gtid    = (long long)blockIdx.x * TILE + tid;
    const long long gstride = (long long)gridDim.x * TILE;

    // positions: 3N floats
    {
        const long long nv = (3LL * n) >> 2;
        const float4* p4 = (const float4*)positions;
        float4* o4 = (float4*)out;
        for (long long idx = gtid; idx < nv; idx += gstride) o4[idx] = p4[idx];
        for (long long idx = nv * 4 + gtid; idx < 3LL * n; idx += gstride)
            out[idx] = positions[idx];
    }
    // alphas: N floats (dst base 48n B -> always 16B aligned)
    {
        const long long nv = (long long)n >> 2;
        const float4* a4 = (const float4*)alphas;
        float4* o4 = (float4*)out_alpha;
        for (long long idx = gtid; idx < nv; idx += gstride) o4[idx] = a4[idx];
        for (long long idx = nv * 4 + gtid; idx < n; idx += gstride)
            out_alpha[idx] = alphas[idx];
    }
}

extern "C" void kernel_launch(void* const* d_in, const int* in_sizes, int n_in,
                              void* d_out, int out_size)
{
    const float* positions = (const float*)d_in[0];
    const float* colors    = (const float*)d_in[1];
    const float* alphas    = (const float*)d_in[2];
    const float* R         = (const float*)d_in[3];
    const float* S         = (const float*)d_in[4];
    float* out = (float*)d_out;

    const int n = in_sizes[2];  // alphas count == N

    const int blocks = (n + TILE - 1) / TILE;
    gs_preprocess_kernel<<<blocks, TILE>>>(positions, colors, alphas, R, S, out, n);
}

// round 8
// speedup vs baseline: 1.1214x; 1.0291x over previous
#include <cuda_runtime.h>
#include <cuda_bf16.h>

// GaussianSplatting preprocess v8 (= champion structure, TILE=128):
//   out = concat(positions[N,3], cov[N,3,3], alphas[N], sh[N,4]) flattened.
//   cov = R (S S^T) R^T per point; sh = [C0, c1*C1, c0*C1, c2*C1].
// Identical phase structure to the 48.9us champion; TILE 256->128 doubles the
// number of independent blocks (stream-parallelism test). All global traffic
// float4-coalesced via smem staging.

#define SH_C0 0.282095f
#define SH_C1 0.488603f

constexpr int TILE = 128;

__global__ void __launch_bounds__(TILE, 16) gs_preprocess_kernel(
    const float* __restrict__ positions,  // [N,3]
    const float* __restrict__ colors,     // [N,3]
    const float* __restrict__ alphas,     // [N]
    const float* __restrict__ R,          // [N,3,3]
    const float* __restrict__ S,          // [N,3,3]
    float* __restrict__ out,              // [17N]
    int n)
{
    __shared__ float sh_col[TILE * 3];
    __shared__ float sh_R[TILE * 9];
    __shared__ float sh_S[TILE * 9];   // reused as cov staging buffer

    const int tid = threadIdx.x;
    const int block0 = blockIdx.x * TILE;

    float* __restrict__ out_cov   = out + 3LL * n;
    float* __restrict__ out_alpha = out + 12LL * n;
    float* __restrict__ out_sh    = out + 13LL * n;

    // ---------------- tiled cov + sh work ----------------
    {
        const int cnt = min(TILE, n - block0);

        if (cnt == TILE) {
            // fully coalesced float4 staging (bases: blk*12B, blk*36B -> 16B aligned)
            const float4* __restrict__ c4 = (const float4*)(colors + (long long)block0 * 3);
            const float4* __restrict__ r4 = (const float4*)(R      + (long long)block0 * 9);
            const float4* __restrict__ s4 = (const float4*)(S      + (long long)block0 * 9);
            float4* shc4 = (float4*)sh_col;
            float4* shr4 = (float4*)sh_R;
            float4* shs4 = (float4*)sh_S;
            if (tid < TILE * 3 / 4) shc4[tid] = c4[tid];          // 96 x 16B
            #pragma unroll
            for (int idx = tid; idx < TILE * 9 / 4; idx += TILE)  // 288 x 16B
                shr4[idx] = r4[idx];
            #pragma unroll
            for (int idx = tid; idx < TILE * 9 / 4; idx += TILE)
                shs4[idx] = s4[idx];
        } else {
            for (int idx = tid; idx < cnt * 3; idx += TILE)
                sh_col[idx] = colors[(long long)block0 * 3 + idx];
            for (int idx = tid; idx < cnt * 9; idx += TILE)
                sh_R[idx] = R[(long long)block0 * 9 + idx];
            for (int idx = tid; idx < cnt * 9; idx += TILE)
                sh_S[idx] = S[(long long)block0 * 9 + idx];
        }
        __syncthreads();

        if (tid < cnt) {
            const long long i = block0 + tid;

            // ---- SH coeffs (direct float4 store when 13n is float4-aligned) ----
            const float c0 = sh_col[tid * 3 + 0];
            const float c1 = sh_col[tid * 3 + 1];
            const float c2 = sh_col[tid * 3 + 2];
            if ((n & 3) == 0) {
                ((float4*)out_sh)[i] =
                    make_float4(SH_C0, c1 * SH_C1, c0 * SH_C1, c2 * SH_C1);
            } else {
                out_sh[4 * i + 0] = SH_C0;
                out_sh[4 * i + 1] = c1 * SH_C1;
                out_sh[4 * i + 2] = c0 * SH_C1;
                out_sh[4 * i + 3] = c2 * SH_C1;
            }

            // ---- load r, s from smem (stride 9 -> bank-conflict-free) ----
            float r[9], s[9];
            #pragma unroll
            for (int k = 0; k < 9; ++k) r[k] = sh_R[tid * 9 + k];
            #pragma unroll
            for (int k = 0; k < 9; ++k) s[k] = sh_S[tid * 9 + k];

            // ---- M = S S^T (symmetric) ----
            const float m00 = s[0]*s[0] + s[1]*s[1] + s[2]*s[2];
            const float m01 = s[0]*s[3] + s[1]*s[4] + s[2]*s[5];
            const float m02 = s[0]*s[6] + s[1]*s[7] + s[2]*s[8];
            const float m11 = s[3]*s[3] + s[4]*s[4] + s[5]*s[5];
            const float m12 = s[3]*s[6] + s[4]*s[7] + s[5]*s[8];
            const float m22 = s[6]*s[6] + s[7]*s[7] + s[8]*s[8];

            // ---- T = R*M, cov = T*R^T; write into sh_S (own region only) ----
            float t[9];
            #pragma unroll
            for (int a = 0; a < 3; ++a) {
                const float ra0 = r[3*a + 0];
                const float ra1 = r[3*a + 1];
                const float ra2 = r[3*a + 2];
                t[3*a + 0] = ra0*m00 + ra1*m01 + ra2*m02;
                t[3*a + 1] = ra0*m01 + ra1*m11 + ra2*m12;
                t[3*a + 2] = ra0*m02 + ra1*m12 + ra2*m22;
            }
            #pragma unroll
            for (int a = 0; a < 3; ++a)
                #pragma unroll
                for (int l = 0; l < 3; ++l)
                    sh_S[tid * 9 + 3*a + l] =
                        t[3*a + 0]*r[3*l + 0] + t[3*a + 1]*r[3*l + 1] + t[3*a + 2]*r[3*l + 2];
        }
        __syncthreads();

        // ---- coalesced cov store (base: 3n + blk*9 floats; aligned iff n%4==0) ----
        if (cnt == TILE && (n & 3) == 0) {
            float4* o4 = (float4*)(out_cov + (long long)block0 * 9);
            const float4* shs4 = (const float4*)sh_S;
            #pragma unroll
            for (int idx = tid; idx < TILE * 9 / 4; idx += TILE)
                o4[idx] = shs4[idx];
        } else {
            for (int idx = tid; idx < cnt * 9; idx += TILE)
                out_cov[(long long)block0 * 9 + idx] = sh_S[idx];
        }
    }

    // ---------------- flat passthrough copies (positions, alphas) ----------------
    const long long gtid    = (long long)blockIdx.x * TILE + tid;
    const long long gstride = (long long)gridDim.x * TILE;

    // positions: 3N floats
    {
        const long long nv = (3LL * n) >> 2;
        const float4* p4 = (const float4*)positions;
        float4* o4 = (float4*)out;
        for (long long idx = gtid; idx < nv; idx += gstride) o4[idx] = p4[idx];
        for (long long idx = nv * 4 + gtid; idx < 3LL * n; idx += gstride)
            out[idx] = positions[idx];
    }
    // alphas: N floats (dst base 48n B -> always 16B aligned)
    {
        const long long nv = (long long)n >> 2;
        const float4* a4 = (const float4*)alphas;
        float4* o4 = (float4*)out_alpha;
        for (long long idx = gtid; idx < nv; idx += gstride) o4[idx] = a4[idx];
        for (long long idx = nv * 4 + gtid; idx < n; idx += gstride)
            out_alpha[idx] = alphas[idx];
    }
}

extern "C" void kernel_launch(void* const* d_in, const int* in_sizes, int n_in,
                              void* d_out, int out_size)
{
    const float* positions = (const float*)d_in[0];
    const float* colors    = (const float*)d_in[1];
    const float* alphas    = (const float*)d_in[2];
    const float* R         = (const float*)d_in[3];
    const float* S         = (const float*)d_in[4];
    float* out = (float*)d_out;

    const int n = in_sizes[2];  // alphas count == N

    const int blocks = (n + TILE - 1) / TILE;
    gs_preprocess_kernel<<<blocks, TILE>>>(positions, colors, alphas, R, S, out, n);
}